// round 6
// baseline (speedup 1.0000x reference)
#include <cuda_runtime.h>
#include <cstddef>

#define H 4
#define C 16
#define DIN 128
#define DOUT 64
#define N_AUTHOR 150000
#define N_PAPER 200000
#define N_OUT 50000
#define E_MAX 1000000
#define NEG 0.2f

// ---------------- scratch (static device arrays; no allocation) ----------------
__device__ float g_l_author[(size_t)N_AUTHOR * DOUT];
__device__ float g_l_paper [(size_t)N_PAPER  * DOUT];
__device__ float g_r_paper [(size_t)N_OUT    * DOUT];   // kept (not used downstream) — harmless
__device__ float g_asrc_w[N_AUTHOR * H];
__device__ float g_asrc_c[N_PAPER  * H];
__device__ float g_adst_w[N_OUT * H];
__device__ float g_adst_c[N_OUT * H];
__device__ float g_emb_w [(size_t)N_OUT * DOUT];        // normalized embeddings
__device__ float g_emb_c [(size_t)N_OUT * DOUT];

// counting-sort scratch
__device__ int g_cnt_w[N_OUT];
__device__ int g_cnt_c[N_OUT];
__device__ int g_off_w[N_OUT + 1];
__device__ int g_off_c[N_OUT + 1];
__device__ int g_cur_w[N_OUT];
__device__ int g_cur_c[N_OUT];
__device__ int g_ssrc_w[E_MAX];
__device__ int g_ssrc_c[E_MAX];

__device__ __forceinline__ float lrelu(float x) { return x > 0.f ? x : NEG * x; }

__device__ __forceinline__ unsigned tf32cvt(float f) {
    unsigned u;
    asm("cvt.rna.tf32.f32 %0, %1;" : "=r"(u) : "f"(f));
    return u;
}

__device__ __forceinline__ void mma_tf32(float* c, const unsigned* a, const unsigned* b) {
    asm volatile(
        "mma.sync.aligned.m16n8k8.row.col.f32.tf32.tf32.f32 "
        "{%0,%1,%2,%3}, {%4,%5,%6,%7}, {%8,%9}, {%0,%1,%2,%3};"
        : "+f"(c[0]), "+f"(c[1]), "+f"(c[2]), "+f"(c[3])
        : "r"(a[0]), "r"(a[1]), "r"(a[2]), "r"(a[3]), "r"(b[0]), "r"(b[1]));
}

// ---------------- zero counts (one launch) ----------------
__global__ void zero_counts(int* cw, int* cc) {
    int i = blockIdx.x * blockDim.x + threadIdx.x;
    if (i < N_OUT) { cw[i] = 0; cc[i] = 0; }
}

// ---------------- counting sort: histogram ----------------
__global__ void hist_kernel(const int* __restrict__ dw, const int* __restrict__ dcst,
                            int* __restrict__ cw, int* __restrict__ cc, int E) {
    int i = blockIdx.x * blockDim.x + threadIdx.x;
    if (i < E)          atomicAdd(&cw[__ldg(&dw[i])], 1);
    else if (i < 2 * E) atomicAdd(&cc[__ldg(&dcst[i - E])], 1);
}

// ---------------- counting sort: exclusive scan (1 block per array) ----------------
#define SCAN_T 1024
__global__ void scan_kernel(const int* __restrict__ cw, int* __restrict__ ow, int* __restrict__ curw,
                            const int* __restrict__ cc, int* __restrict__ oc, int* __restrict__ curc,
                            int n) {
    const int* counts = (blockIdx.x == 0) ? cw : cc;
    int* offsets      = (blockIdx.x == 0) ? ow : oc;
    int* cursor       = (blockIdx.x == 0) ? curw : curc;

    __shared__ int warp_sums[32];
    __shared__ int warp_off[32];
    __shared__ int carry_s;
    int tid  = threadIdx.x;
    int wid  = tid >> 5;
    int lane = tid & 31;
    if (tid == 0) carry_s = 0;
    __syncthreads();

    for (int base = 0; base < n; base += SCAN_T) {
        int i = base + tid;
        int v = (i < n) ? counts[i] : 0;
        // warp inclusive scan
        int x = v;
#pragma unroll
        for (int off = 1; off < 32; off <<= 1) {
            int t = __shfl_up_sync(0xffffffffu, x, off);
            if (lane >= off) x += t;
        }
        if (lane == 31) warp_sums[wid] = x;
        __syncthreads();
        if (wid == 0) {
            int s = warp_sums[lane];
            int y = s;
#pragma unroll
            for (int off = 1; off < 32; off <<= 1) {
                int t = __shfl_up_sync(0xffffffffu, y, off);
                if (lane >= off) y += t;
            }
            warp_off[lane] = y - s;     // exclusive warp offsets
        }
        __syncthreads();
        int carry = carry_s;
        int excl = x - v + warp_off[wid] + carry;
        if (i < n) { offsets[i] = excl; cursor[i] = excl; }
        __syncthreads();
        if (tid == SCAN_T - 1) carry_s = carry + warp_off[31] + warp_sums[31] - warp_sums[31] + x; // carry + tile total
        // tile total = warp_off[31] + warp_sums[31]; but x (tid=1023,lane=31) == warp_sums[31]
        __syncthreads();
    }
    if (tid == 0) offsets[n] = carry_s;
}

// ---------------- counting sort: scatter ----------------
__global__ void scatter_kernel(const int* __restrict__ sw, const int* __restrict__ dw,
                               const int* __restrict__ sc, const int* __restrict__ dcst,
                               int* __restrict__ curw, int* __restrict__ curc,
                               int* __restrict__ outw, int* __restrict__ outc, int E) {
    int i = blockIdx.x * blockDim.x + threadIdx.x;
    if (i < E) {
        int pos = atomicAdd(&curw[__ldg(&dw[i])], 1);
        outw[pos] = __ldg(&sw[i]);
    } else if (i < 2 * E) {
        int j = i - E;
        int pos = atomicAdd(&curc[__ldg(&dcst[j])], 1);
        outc[pos] = __ldg(&sc[j]);
    }
}

// ---------------- projection GEMM via tf32 tensor cores (unchanged from R5) ----------------
#define TMR 128
#define KC 16
#define XT_S 136
#define WS_S 72

__global__ void __launch_bounds__(256)
proj_kernel(const float* __restrict__ X,
            const float* __restrict__ Wm,
            const float* __restrict__ bias,
            float* __restrict__ Out, int N,
            const float* __restrict__ attnA, int offA, float* __restrict__ alphaA,
            const float* __restrict__ attnB, int offB, float* __restrict__ alphaB)
{
    __shared__ unsigned xsT[2][KC * XT_S];
    __shared__ unsigned wsm[2][KC * WS_S];

    const int tid  = threadIdx.x;
    const int w    = tid >> 5;
    const int lane = tid & 31;
    const int gid  = lane >> 2;
    const int tig  = lane & 3;
    const int row0 = blockIdx.x * TMR;

    float4 xr[4];
    float4 wr[2];
    const int wk  = (tid - 128) >> 3;
    const int wn8 = (tid - 128) & 7;

    auto load_regs = [&](int kc) {
        if (tid < TMR) {
            int grow = row0 + tid;
            if (grow < N) {
                const float4* xp = (const float4*)(X + (size_t)grow * DIN + kc * KC);
                xr[0] = xp[0]; xr[1] = xp[1]; xr[2] = xp[2]; xr[3] = xp[3];
            } else {
                xr[0] = xr[1] = xr[2] = xr[3] = make_float4(0.f, 0.f, 0.f, 0.f);
            }
        } else {
            const float4* wp = (const float4*)(Wm + (size_t)(kc * KC + wk) * DOUT + wn8 * 8);
            wr[0] = wp[0]; wr[1] = wp[1];
        }
    };
    auto store_smem = [&](int b) {
        if (tid < TMR) {
            float v[16] = {xr[0].x, xr[0].y, xr[0].z, xr[0].w,
                           xr[1].x, xr[1].y, xr[1].z, xr[1].w,
                           xr[2].x, xr[2].y, xr[2].z, xr[2].w,
                           xr[3].x, xr[3].y, xr[3].z, xr[3].w};
#pragma unroll
            for (int k = 0; k < 16; k++)
                xsT[b][k * XT_S + tid] = tf32cvt(v[k]);
        } else {
            unsigned* wp = &wsm[b][wk * WS_S + wn8 * 8];
            wp[0] = tf32cvt(wr[0].x); wp[1] = tf32cvt(wr[0].y);
            wp[2] = tf32cvt(wr[0].z); wp[3] = tf32cvt(wr[0].w);
            wp[4] = tf32cvt(wr[1].x); wp[5] = tf32cvt(wr[1].y);
            wp[6] = tf32cvt(wr[1].z); wp[7] = tf32cvt(wr[1].w);
        }
    };

    float acc[8][4];
#pragma unroll
    for (int n8 = 0; n8 < 8; n8++)
#pragma unroll
        for (int i = 0; i < 4; i++) acc[n8][i] = 0.f;

    load_regs(0);
    store_smem(0);
    __syncthreads();

    const int r0 = w * 16;
    for (int kc = 0; kc < DIN / KC; kc++) {
        if (kc < 7) load_regs(kc + 1);
        const int b = kc & 1;

#pragma unroll
        for (int ks = 0; ks < KC; ks += 8) {
            unsigned a[4], bb[8][2];
            a[0] = xsT[b][(ks + tig)     * XT_S + r0 + gid];
            a[1] = xsT[b][(ks + tig)     * XT_S + r0 + gid + 8];
            a[2] = xsT[b][(ks + tig + 4) * XT_S + r0 + gid];
            a[3] = xsT[b][(ks + tig + 4) * XT_S + r0 + gid + 8];
#pragma unroll
            for (int n8 = 0; n8 < 8; n8++) {
                bb[n8][0] = wsm[b][(ks + tig)     * WS_S + n8 * 8 + gid];
                bb[n8][1] = wsm[b][(ks + tig + 4) * WS_S + n8 * 8 + gid];
            }
#pragma unroll
            for (int n8 = 0; n8 < 8; n8++) mma_tf32(acc[n8], a, bb[n8]);
        }

        if (kc < 7) {
            __syncthreads();
            store_smem((kc + 1) & 1);
            __syncthreads();
        }
    }

    const int row_lo = row0 + r0 + gid;
    const int row_hi = row_lo + 8;

#pragma unroll
    for (int n8 = 0; n8 < 8; n8++) {
        int col = n8 * 8 + 2 * tig;
        float b0 = __ldg(&bias[col]), b1 = __ldg(&bias[col + 1]);
        acc[n8][0] += b0; acc[n8][1] += b1;
        acc[n8][2] += b0; acc[n8][3] += b1;
        if (row_lo < N)
            *(float2*)(Out + (size_t)row_lo * DOUT + col) = make_float2(acc[n8][0], acc[n8][1]);
        if (row_hi < N)
            *(float2*)(Out + (size_t)row_hi * DOUT + col) = make_float2(acc[n8][2], acc[n8][3]);
    }

    if (alphaA || alphaB) {
#pragma unroll
        for (int h = 0; h < 4; h++) {
            float sAlo = 0.f, sAhi = 0.f, sBlo = 0.f, sBhi = 0.f;
#pragma unroll
            for (int q = 0; q < 2; q++) {
                int n8 = 2 * h + q;
#pragma unroll
                for (int d = 0; d < 2; d++) {
                    int c = q * 8 + 2 * tig + d;
                    float vlo = lrelu(acc[n8][d]);
                    float vhi = lrelu(acc[n8][2 + d]);
                    if (alphaA) {
                        float av = __ldg(&attnA[h * 2 * C + offA + c]);
                        sAlo += vlo * av; sAhi += vhi * av;
                    }
                    if (alphaB) {
                        float bv = __ldg(&attnB[h * 2 * C + offB + c]);
                        sBlo += vlo * bv; sBhi += vhi * bv;
                    }
                }
            }
            sAlo += __shfl_xor_sync(0xffffffffu, sAlo, 1);
            sAlo += __shfl_xor_sync(0xffffffffu, sAlo, 2);
            sAhi += __shfl_xor_sync(0xffffffffu, sAhi, 1);
            sAhi += __shfl_xor_sync(0xffffffffu, sAhi, 2);
            sBlo += __shfl_xor_sync(0xffffffffu, sBlo, 1);
            sBlo += __shfl_xor_sync(0xffffffffu, sBlo, 2);
            sBhi += __shfl_xor_sync(0xffffffffu, sBhi, 1);
            sBhi += __shfl_xor_sync(0xffffffffu, sBhi, 2);
            if (tig == 0) {
                if (alphaA) {
                    if (row_lo < N) alphaA[row_lo * H + h] = sAlo;
                    if (row_hi < N) alphaA[row_hi * H + h] = sAhi;
                }
                if (alphaB) {
                    if (row_lo < N) alphaB[row_lo * H + h] = sBlo;
                    if (row_hi < N) alphaB[row_hi * H + h] = sBhi;
                }
            }
        }
    }
}

// ---------------- segmented gather: one warp per dst, no atomics ----------------
// lane owns cols lane*2, lane*2+1; head h = lane>>3.
// emb written ALREADY NORMALIZED: sum(ea*x)/sum(ea).
__global__ void __launch_bounds__(256)
gather_kernel(const int* __restrict__ ssrc, const int* __restrict__ offsets,
              const float* __restrict__ asrc, const float* __restrict__ adst,
              const float* __restrict__ lsrc, float* __restrict__ emb)
{
    int wg = (blockIdx.x * blockDim.x + threadIdx.x) >> 5;
    if (wg >= N_OUT) return;
    int lane = threadIdx.x & 31;
    int d = wg;
    int h = lane >> 3;

    int beg = __ldg(&offsets[d]);
    int end = __ldg(&offsets[d + 1]);
    float ad = __ldg(&adst[d * H + h]);

    float a0 = 0.f, a1 = 0.f, se = 0.f;
    int e = beg;
    for (; e + 1 < end; e += 2) {
        int s0 = __ldg(&ssrc[e]);
        int s1 = __ldg(&ssrc[e + 1]);
        float ea0 = __expf(__ldg(&asrc[s0 * H + h]) + ad);
        float ea1 = __expf(__ldg(&asrc[s1 * H + h]) + ad);
        float2 v0 = *(const float2*)(lsrc + (size_t)s0 * DOUT + lane * 2);
        float2 v1 = *(const float2*)(lsrc + (size_t)s1 * DOUT + lane * 2);
        a0 = fmaf(ea0, v0.x, a0); a1 = fmaf(ea0, v0.y, a1);
        a0 = fmaf(ea1, v1.x, a0); a1 = fmaf(ea1, v1.y, a1);
        se += ea0 + ea1;
    }
    if (e < end) {
        int s0 = __ldg(&ssrc[e]);
        float ea0 = __expf(__ldg(&asrc[s0 * H + h]) + ad);
        float2 v0 = *(const float2*)(lsrc + (size_t)s0 * DOUT + lane * 2);
        a0 = fmaf(ea0, v0.x, a0); a1 = fmaf(ea0, v0.y, a1);
        se += ea0;
    }
    float inv = 1.f / (se + 1e-16f);
    *(float2*)(emb + (size_t)d * DOUT + lane * 2) = make_float2(a0 * inv, a1 * inv);
}

// ---------------- semantic attention + relu (emb pre-normalized) ----------------
__global__ void final_kernel(const float* __restrict__ emb_w,
                             const float* __restrict__ emb_c,
                             const float* __restrict__ lpap,
                             const float* __restrict__ rel_l, const float* __restrict__ rel_r,
                             float* __restrict__ out)
{
    int idx = blockIdx.x * blockDim.x + threadIdx.x;
    if (idx >= N_OUT * H) return;
    int n = idx >> 2, h = idx & 3;
    size_t base = (size_t)n * DOUT + h * 16;

    float w[16], cc[16], sf[16];
#pragma unroll
    for (int i = 0; i < 4; i++) {
        float4 vw = *(const float4*)(emb_w + base + i * 4);
        float4 vc = *(const float4*)(emb_c + base + i * 4);
        float4 vs = *(const float4*)(lpap  + base + i * 4);
        w[i*4+0] = vw.x; w[i*4+1] = vw.y; w[i*4+2] = vw.z; w[i*4+3] = vw.w;
        cc[i*4+0] = vc.x; cc[i*4+1] = vc.y; cc[i*4+2] = vc.z; cc[i*4+3] = vc.w;
        sf[i*4+0] = vs.x; sf[i*4+1] = vs.y; sf[i*4+2] = vs.z; sf[i*4+3] = vs.w;
    }

    float al = 0.f, a0 = 0.f, a1 = 0.f, a2 = 0.f;
#pragma unroll
    for (int i = 0; i < 16; i++) {
        al += sf[i] * __ldg(&rel_l[h * C + i]);
        a0 += w[i]  * __ldg(&rel_r[0 * H * C + h * C + i]);
        a1 += cc[i] * __ldg(&rel_r[1 * H * C + h * C + i]);
        a2 += sf[i] * __ldg(&rel_r[2 * H * C + h * C + i]);
    }
    float s0 = lrelu(al + a0), s1 = lrelu(al + a1), s2 = lrelu(al + a2);
    float mx = fmaxf(s0, fmaxf(s1, s2));
    float e0 = __expf(s0 - mx), e1 = __expf(s1 - mx), e2 = __expf(s2 - mx);
    float inv = 1.f / (e0 + e1 + e2);
    float b0 = e0 * inv, b1 = e1 * inv, b2 = e2 * inv;

    float4* op = (float4*)(out + base);
#pragma unroll
    for (int i = 0; i < 4; i++) {
        float4 o;
        o.x = fmaxf(0.f, b0 * w[i*4+0] + b1 * cc[i*4+0] + b2 * sf[i*4+0]);
        o.y = fmaxf(0.f, b0 * w[i*4+1] + b1 * cc[i*4+1] + b2 * sf[i*4+1]);
        o.z = fmaxf(0.f, b0 * w[i*4+2] + b1 * cc[i*4+2] + b2 * sf[i*4+2]);
        o.w = fmaxf(0.f, b0 * w[i*4+3] + b1 * cc[i*4+3] + b2 * sf[i*4+3]);
        op[i] = o;
    }
}

// ---------------- launch ----------------
extern "C" void kernel_launch(void* const* d_in, const int* in_sizes, int n_in,
                              void* d_out, int out_size)
{
    const float* x_author   = (const float*)d_in[0];
    const float* x_paper    = (const float*)d_in[1];
    const float* W_l_author = (const float*)d_in[2];
    const float* b_l_author = (const float*)d_in[3];
    const float* W_l_paper  = (const float*)d_in[4];
    const float* b_l_paper  = (const float*)d_in[5];
    const float* W_r_paper  = (const float*)d_in[6];
    const float* b_r_paper  = (const float*)d_in[7];
    const float* attn_writes = (const float*)d_in[8];
    const float* attn_cites  = (const float*)d_in[9];
    const float* rel_l = (const float*)d_in[10];
    const float* rel_r = (const float*)d_in[11];
    const int* src_w = (const int*)d_in[12];
    const int* dst_w = (const int*)d_in[13];
    const int* src_c = (const int*)d_in[14];
    const int* dst_c = (const int*)d_in[15];
    const int E = in_sizes[12];
    float* out = (float*)d_out;

    float *l_author, *l_paper, *r_paper, *asw, *asc, *adw, *adc, *ew, *ec;
    int *cw, *ccnt, *ow, *oc, *curw, *curc, *ssw, *ssc;
    cudaGetSymbolAddress((void**)&l_author, g_l_author);
    cudaGetSymbolAddress((void**)&l_paper,  g_l_paper);
    cudaGetSymbolAddress((void**)&r_paper,  g_r_paper);
    cudaGetSymbolAddress((void**)&asw, g_asrc_w);
    cudaGetSymbolAddress((void**)&asc, g_asrc_c);
    cudaGetSymbolAddress((void**)&adw, g_adst_w);
    cudaGetSymbolAddress((void**)&adc, g_adst_c);
    cudaGetSymbolAddress((void**)&ew,  g_emb_w);
    cudaGetSymbolAddress((void**)&ec,  g_emb_c);
    cudaGetSymbolAddress((void**)&cw,   g_cnt_w);
    cudaGetSymbolAddress((void**)&ccnt, g_cnt_c);
    cudaGetSymbolAddress((void**)&ow,   g_off_w);
    cudaGetSymbolAddress((void**)&oc,   g_off_c);
    cudaGetSymbolAddress((void**)&curw, g_cur_w);
    cudaGetSymbolAddress((void**)&curc, g_cur_c);
    cudaGetSymbolAddress((void**)&ssw,  g_ssrc_w);
    cudaGetSymbolAddress((void**)&ssc,  g_ssrc_c);

    // counting sort of both edge lists by dst (independent of projections)
    zero_counts<<<(N_OUT + 255) / 256, 256>>>(cw, ccnt);
    hist_kernel<<<(2 * E + 255) / 256, 256>>>(dst_w, dst_c, cw, ccnt, E);
    scan_kernel<<<2, SCAN_T>>>(cw, ow, curw, ccnt, oc, curc, N_OUT);
    scatter_kernel<<<(2 * E + 255) / 256, 256>>>(src_w, dst_w, src_c, dst_c,
                                                 curw, curc, ssw, ssc, E);

    // projections + per-node attention logits in epilogue (tf32 tensor cores)
    proj_kernel<<<(N_AUTHOR + TMR - 1) / TMR, 256>>>(
        x_author, W_l_author, b_l_author, l_author, N_AUTHOR,
        attn_writes, C, asw, nullptr, 0, nullptr);
    proj_kernel<<<(N_PAPER + TMR - 1) / TMR, 256>>>(
        x_paper, W_l_paper, b_l_paper, l_paper, N_PAPER,
        attn_cites, C, asc, nullptr, 0, nullptr);
    proj_kernel<<<(N_OUT + TMR - 1) / TMR, 256>>>(
        x_paper, W_r_paper, b_r_paper, r_paper, N_OUT,
        attn_writes, 0, adw, attn_cites, 0, adc);

    // segmented softmax-weighted aggregation, no atomics
    {
        int blocks = (N_OUT * 32 + 255) / 256;
        gather_kernel<<<blocks, 256>>>(ssw, ow, asw, adw, l_author, ew);
        gather_kernel<<<blocks, 256>>>(ssc, oc, asc, adc, l_paper, ec);
    }

    // semantic attention over {writes, cites, self}
    final_kernel<<<(N_OUT * H + 255) / 256, 256>>>(ew, ec, l_paper, rel_l, rel_r, out);
}

// round 7
// speedup vs baseline: 1.2298x; 1.2298x over previous
#include <cuda_runtime.h>
#include <cstddef>

#define H 4
#define C 16
#define DIN 128
#define DOUT 64
#define N_AUTHOR 150000
#define N_PAPER 200000
#define N_OUT 50000
#define E_MAX 1000000
#define NEG 0.2f

#define CHUNK 2048
#define NCHUNKS ((N_OUT + CHUNK - 1) / CHUNK)   // 25

// ---------------- scratch (static device arrays; no allocation) ----------------
__device__ float g_l_author[(size_t)N_AUTHOR * DOUT];
__device__ float g_l_paper [(size_t)N_PAPER  * DOUT];
__device__ float g_asrc_w[N_AUTHOR * H];
__device__ float g_asrc_c[N_PAPER  * H];
__device__ float g_emb_w [(size_t)N_OUT * DOUT];   // normalized embeddings
__device__ float g_emb_c [(size_t)N_OUT * DOUT];

// counting-sort scratch
__device__ int g_cnt_w[N_OUT];
__device__ int g_cnt_c[N_OUT];
__device__ int g_off_w[N_OUT + 1];
__device__ int g_off_c[N_OUT + 1];
__device__ int g_cur_w[N_OUT];
__device__ int g_cur_c[N_OUT];
__device__ int g_ssrc_w[E_MAX];
__device__ int g_ssrc_c[E_MAX];
__device__ int g_blocksums[2 * 32];
__device__ int g_chunkbase[2 * 32];

__device__ __forceinline__ float lrelu(float x) { return x > 0.f ? x : NEG * x; }

__device__ __forceinline__ unsigned tf32cvt(float f) {
    unsigned u;
    asm("cvt.rna.tf32.f32 %0, %1;" : "=r"(u) : "f"(f));
    return u;
}

__device__ __forceinline__ void mma_tf32(float* c, const unsigned* a, const unsigned* b) {
    asm volatile(
        "mma.sync.aligned.m16n8k8.row.col.f32.tf32.tf32.f32 "
        "{%0,%1,%2,%3}, {%4,%5,%6,%7}, {%8,%9}, {%0,%1,%2,%3};"
        : "+f"(c[0]), "+f"(c[1]), "+f"(c[2]), "+f"(c[3])
        : "r"(a[0]), "r"(a[1]), "r"(a[2]), "r"(a[3]), "r"(b[0]), "r"(b[1]));
}

// ---------------- zero counts ----------------
__global__ void zero_counts(int* cw, int* cc) {
    int i = blockIdx.x * blockDim.x + threadIdx.x;
    if (i < N_OUT) { cw[i] = 0; cc[i] = 0; }
}

// ---------------- counting sort: histogram ----------------
__global__ void hist_kernel(const int* __restrict__ dw, const int* __restrict__ dcst,
                            int* __restrict__ cw, int* __restrict__ cc, int E) {
    int i = blockIdx.x * blockDim.x + threadIdx.x;
    if (i < E)          atomicAdd(&cw[__ldg(&dw[i])], 1);
    else if (i < 2 * E) atomicAdd(&cc[__ldg(&dcst[i - E])], 1);
}

// ---------------- hierarchical exclusive scan ----------------
// scanA: per-chunk local exclusive scan (grid = NCHUNKS x 2), 256 thr x 8 elems
__global__ void __launch_bounds__(256)
scanA(const int* __restrict__ cw, const int* __restrict__ cc,
      int* __restrict__ ow, int* __restrict__ oc, int* __restrict__ blocksums, int n)
{
    int arr = blockIdx.y;
    const int* counts = arr ? cc : cw;
    int* off = arr ? oc : ow;
    int tid = threadIdx.x, lane = tid & 31, wid = tid >> 5;
    int base = blockIdx.x * CHUNK + tid * 8;

    int v[8], s = 0;
#pragma unroll
    for (int j = 0; j < 8; j++) {
        int i = base + j;
        v[j] = (i < n) ? counts[i] : 0;
        s += v[j];
    }
    int x = s;
#pragma unroll
    for (int o = 1; o < 32; o <<= 1) {
        int t = __shfl_up_sync(0xffffffffu, x, o);
        if (lane >= o) x += t;
    }
    int warp_excl = x - s;

    __shared__ int wsum[8], woff[8];
    if (lane == 31) wsum[wid] = x;
    __syncthreads();
    if (tid < 8) {
        int t = 0;
        for (int k = 0; k < tid; k++) t += wsum[k];
        woff[tid] = t;
    }
    __syncthreads();

    int run = woff[wid] + warp_excl;
#pragma unroll
    for (int j = 0; j < 8; j++) {
        int i = base + j;
        if (i < n) off[i] = run;
        run += v[j];
    }
    if (tid == 255) blocksums[arr * 32 + blockIdx.x] = woff[7] + wsum[7];
}

// scanB: scan the chunk sums (1 block, 2 warps)
__global__ void scanB(int* __restrict__ blocksums, int* __restrict__ chunkbase,
                      int* __restrict__ ow, int* __restrict__ oc, int n)
{
    int wid = threadIdx.x >> 5, lane = threadIdx.x & 31;
    if (wid < 2) {
        int v = (lane < NCHUNKS) ? blocksums[wid * 32 + lane] : 0;
        int x = v;
#pragma unroll
        for (int o = 1; o < 32; o <<= 1) {
            int t = __shfl_up_sync(0xffffffffu, x, o);
            if (lane >= o) x += t;
        }
        if (lane < NCHUNKS) chunkbase[wid * 32 + lane] = x - v;
        if (lane == NCHUNKS - 1) {
            if (wid == 0) ow[n] = x; else oc[n] = x;
        }
    }
}

// scanC: add chunk bases, write cursors
__global__ void __launch_bounds__(256)
scanC(int* __restrict__ ow, int* __restrict__ oc,
      int* __restrict__ curw, int* __restrict__ curc,
      const int* __restrict__ chunkbase, int n)
{
    int arr = blockIdx.y;
    int* off = arr ? oc : ow;
    int* cur = arr ? curc : curw;
    int cb = __ldg(&chunkbase[arr * 32 + blockIdx.x]);
#pragma unroll
    for (int j = 0; j < 8; j++) {
        int i = blockIdx.x * CHUNK + j * 256 + threadIdx.x;
        if (i < n) {
            int t = off[i] + cb;
            off[i] = t;
            cur[i] = t;
        }
    }
}

// ---------------- counting sort: scatter ----------------
__global__ void scatter_kernel(const int* __restrict__ sw, const int* __restrict__ dw,
                               const int* __restrict__ sc, const int* __restrict__ dcst,
                               int* __restrict__ curw, int* __restrict__ curc,
                               int* __restrict__ outw, int* __restrict__ outc, int E) {
    int i = blockIdx.x * blockDim.x + threadIdx.x;
    if (i < E) {
        int pos = atomicAdd(&curw[__ldg(&dw[i])], 1);
        outw[pos] = __ldg(&sw[i]);
    } else if (i < 2 * E) {
        int j = i - E;
        int pos = atomicAdd(&curc[__ldg(&dcst[j])], 1);
        outc[pos] = __ldg(&sc[j]);
    }
}

// ---------------- projection GEMM via tf32 tensor cores ----------------
#define TMR 128
#define KC 16
#define XT_S 136
#define WS_S 72

__global__ void __launch_bounds__(256)
proj_kernel(const float* __restrict__ X,
            const float* __restrict__ Wm,
            const float* __restrict__ bias,
            float* __restrict__ Out, int N,
            const float* __restrict__ attnA, int offA, float* __restrict__ alphaA)
{
    __shared__ unsigned xsT[2][KC * XT_S];
    __shared__ unsigned wsm[2][KC * WS_S];

    const int tid  = threadIdx.x;
    const int w    = tid >> 5;
    const int lane = tid & 31;
    const int gid  = lane >> 2;
    const int tig  = lane & 3;
    const int row0 = blockIdx.x * TMR;

    float4 xr[4];
    float4 wr[2];
    const int wk  = (tid - 128) >> 3;
    const int wn8 = (tid - 128) & 7;

    auto load_regs = [&](int kc) {
        if (tid < TMR) {
            int grow = row0 + tid;
            if (grow < N) {
                const float4* xp = (const float4*)(X + (size_t)grow * DIN + kc * KC);
                xr[0] = xp[0]; xr[1] = xp[1]; xr[2] = xp[2]; xr[3] = xp[3];
            } else {
                xr[0] = xr[1] = xr[2] = xr[3] = make_float4(0.f, 0.f, 0.f, 0.f);
            }
        } else {
            const float4* wp = (const float4*)(Wm + (size_t)(kc * KC + wk) * DOUT + wn8 * 8);
            wr[0] = wp[0]; wr[1] = wp[1];
        }
    };
    auto store_smem = [&](int b) {
        if (tid < TMR) {
            float v[16] = {xr[0].x, xr[0].y, xr[0].z, xr[0].w,
                           xr[1].x, xr[1].y, xr[1].z, xr[1].w,
                           xr[2].x, xr[2].y, xr[2].z, xr[2].w,
                           xr[3].x, xr[3].y, xr[3].z, xr[3].w};
#pragma unroll
            for (int k = 0; k < 16; k++)
                xsT[b][k * XT_S + tid] = tf32cvt(v[k]);
        } else {
            unsigned* wp = &wsm[b][wk * WS_S + wn8 * 8];
            wp[0] = tf32cvt(wr[0].x); wp[1] = tf32cvt(wr[0].y);
            wp[2] = tf32cvt(wr[0].z); wp[3] = tf32cvt(wr[0].w);
            wp[4] = tf32cvt(wr[1].x); wp[5] = tf32cvt(wr[1].y);
            wp[6] = tf32cvt(wr[1].z); wp[7] = tf32cvt(wr[1].w);
        }
    };

    float acc[8][4];
#pragma unroll
    for (int n8 = 0; n8 < 8; n8++)
#pragma unroll
        for (int i = 0; i < 4; i++) acc[n8][i] = 0.f;

    load_regs(0);
    store_smem(0);
    __syncthreads();

    const int r0 = w * 16;
    for (int kc = 0; kc < DIN / KC; kc++) {
        if (kc < 7) load_regs(kc + 1);
        const int b = kc & 1;

#pragma unroll
        for (int ks = 0; ks < KC; ks += 8) {
            unsigned a[4], bb[8][2];
            a[0] = xsT[b][(ks + tig)     * XT_S + r0 + gid];
            a[1] = xsT[b][(ks + tig)     * XT_S + r0 + gid + 8];
            a[2] = xsT[b][(ks + tig + 4) * XT_S + r0 + gid];
            a[3] = xsT[b][(ks + tig + 4) * XT_S + r0 + gid + 8];
#pragma unroll
            for (int n8 = 0; n8 < 8; n8++) {
                bb[n8][0] = wsm[b][(ks + tig)     * WS_S + n8 * 8 + gid];
                bb[n8][1] = wsm[b][(ks + tig + 4) * WS_S + n8 * 8 + gid];
            }
#pragma unroll
            for (int n8 = 0; n8 < 8; n8++) mma_tf32(acc[n8], a, bb[n8]);
        }

        if (kc < 7) {
            __syncthreads();
            store_smem((kc + 1) & 1);
            __syncthreads();
        }
    }

    const int row_lo = row0 + r0 + gid;
    const int row_hi = row_lo + 8;

#pragma unroll
    for (int n8 = 0; n8 < 8; n8++) {
        int col = n8 * 8 + 2 * tig;
        float b0 = __ldg(&bias[col]), b1 = __ldg(&bias[col + 1]);
        acc[n8][0] += b0; acc[n8][1] += b1;
        acc[n8][2] += b0; acc[n8][3] += b1;
        if (row_lo < N)
            *(float2*)(Out + (size_t)row_lo * DOUT + col) = make_float2(acc[n8][0], acc[n8][1]);
        if (row_hi < N)
            *(float2*)(Out + (size_t)row_hi * DOUT + col) = make_float2(acc[n8][2], acc[n8][3]);
    }

#pragma unroll
    for (int h = 0; h < 4; h++) {
        float sAlo = 0.f, sAhi = 0.f;
#pragma unroll
        for (int q = 0; q < 2; q++) {
            int n8 = 2 * h + q;
#pragma unroll
            for (int d = 0; d < 2; d++) {
                int c = q * 8 + 2 * tig + d;
                float av = __ldg(&attnA[h * 2 * C + offA + c]);
                sAlo += lrelu(acc[n8][d])     * av;
                sAhi += lrelu(acc[n8][2 + d]) * av;
            }
        }
        sAlo += __shfl_xor_sync(0xffffffffu, sAlo, 1);
        sAlo += __shfl_xor_sync(0xffffffffu, sAlo, 2);
        sAhi += __shfl_xor_sync(0xffffffffu, sAhi, 1);
        sAhi += __shfl_xor_sync(0xffffffffu, sAhi, 2);
        if (tig == 0) {
            if (row_lo < N) alphaA[row_lo * H + h] = sAlo;
            if (row_hi < N) alphaA[row_hi * H + h] = sAhi;
        }
    }
}

// ---------------- segmented gather: one warp per dst, no atomics ----------------
// alpha_dst cancels in the segment softmax, so only exp(asrc) is needed.
// lane owns cols lane*2, lane*2+1; head h = lane>>3. emb written NORMALIZED.
__global__ void __launch_bounds__(256)
gather_kernel(const int* __restrict__ ssrc, const int* __restrict__ offsets,
              const float* __restrict__ asrc,
              const float* __restrict__ lsrc, float* __restrict__ emb)
{
    int wg = (blockIdx.x * blockDim.x + threadIdx.x) >> 5;
    if (wg >= N_OUT) return;
    int lane = threadIdx.x & 31;
    int h = lane >> 3;

    int beg = __ldg(&offsets[wg]);
    int end = __ldg(&offsets[wg + 1]);

    float a0 = 0.f, a1 = 0.f, se = 0.f;
    int e = beg;
    for (; e + 4 <= end; e += 4) {
        int s0 = __ldg(&ssrc[e]);
        int s1 = __ldg(&ssrc[e + 1]);
        int s2 = __ldg(&ssrc[e + 2]);
        int s3 = __ldg(&ssrc[e + 3]);
        float ea0 = __expf(__ldg(&asrc[s0 * H + h]));
        float ea1 = __expf(__ldg(&asrc[s1 * H + h]));
        float ea2 = __expf(__ldg(&asrc[s2 * H + h]));
        float ea3 = __expf(__ldg(&asrc[s3 * H + h]));
        float2 v0 = *(const float2*)(lsrc + (size_t)s0 * DOUT + lane * 2);
        float2 v1 = *(const float2*)(lsrc + (size_t)s1 * DOUT + lane * 2);
        float2 v2 = *(const float2*)(lsrc + (size_t)s2 * DOUT + lane * 2);
        float2 v3 = *(const float2*)(lsrc + (size_t)s3 * DOUT + lane * 2);
        a0 = fmaf(ea0, v0.x, a0); a1 = fmaf(ea0, v0.y, a1);
        a0 = fmaf(ea1, v1.x, a0); a1 = fmaf(ea1, v1.y, a1);
        a0 = fmaf(ea2, v2.x, a0); a1 = fmaf(ea2, v2.y, a1);
        a0 = fmaf(ea3, v3.x, a0); a1 = fmaf(ea3, v3.y, a1);
        se += ea0 + ea1 + ea2 + ea3;
    }
    for (; e < end; e++) {
        int s0 = __ldg(&ssrc[e]);
        float ea0 = __expf(__ldg(&asrc[s0 * H + h]));
        float2 v0 = *(const float2*)(lsrc + (size_t)s0 * DOUT + lane * 2);
        a0 = fmaf(ea0, v0.x, a0); a1 = fmaf(ea0, v0.y, a1);
        se += ea0;
    }
    float inv = 1.f / (se + 1e-16f);
    *(float2*)(emb + (size_t)wg * DOUT + lane * 2) = make_float2(a0 * inv, a1 * inv);
}

// ---------------- semantic attention + relu (emb pre-normalized) ----------------
__global__ void final_kernel(const float* __restrict__ emb_w,
                             const float* __restrict__ emb_c,
                             const float* __restrict__ lpap,
                             const float* __restrict__ rel_l, const float* __restrict__ rel_r,
                             float* __restrict__ out)
{
    int idx = blockIdx.x * blockDim.x + threadIdx.x;
    if (idx >= N_OUT * H) return;
    int n = idx >> 2, h = idx & 3;
    size_t base = (size_t)n * DOUT + h * 16;

    float w[16], cc[16], sf[16];
#pragma unroll
    for (int i = 0; i < 4; i++) {
        float4 vw = *(const float4*)(emb_w + base + i * 4);
        float4 vc = *(const float4*)(emb_c + base + i * 4);
        float4 vs = *(const float4*)(lpap  + base + i * 4);
        w[i*4+0] = vw.x; w[i*4+1] = vw.y; w[i*4+2] = vw.z; w[i*4+3] = vw.w;
        cc[i*4+0] = vc.x; cc[i*4+1] = vc.y; cc[i*4+2] = vc.z; cc[i*4+3] = vc.w;
        sf[i*4+0] = vs.x; sf[i*4+1] = vs.y; sf[i*4+2] = vs.z; sf[i*4+3] = vs.w;
    }

    float al = 0.f, a0 = 0.f, a1 = 0.f, a2 = 0.f;
#pragma unroll
    for (int i = 0; i < 16; i++) {
        al += sf[i] * __ldg(&rel_l[h * C + i]);
        a0 += w[i]  * __ldg(&rel_r[0 * H * C + h * C + i]);
        a1 += cc[i] * __ldg(&rel_r[1 * H * C + h * C + i]);
        a2 += sf[i] * __ldg(&rel_r[2 * H * C + h * C + i]);
    }
    float s0 = lrelu(al + a0), s1 = lrelu(al + a1), s2 = lrelu(al + a2);
    float mx = fmaxf(s0, fmaxf(s1, s2));
    float e0 = __expf(s0 - mx), e1 = __expf(s1 - mx), e2 = __expf(s2 - mx);
    float inv = 1.f / (e0 + e1 + e2);
    float b0 = e0 * inv, b1 = e1 * inv, b2 = e2 * inv;

    float4* op = (float4*)(out + base);
#pragma unroll
    for (int i = 0; i < 4; i++) {
        float4 o;
        o.x = fmaxf(0.f, b0 * w[i*4+0] + b1 * cc[i*4+0] + b2 * sf[i*4+0]);
        o.y = fmaxf(0.f, b0 * w[i*4+1] + b1 * cc[i*4+1] + b2 * sf[i*4+1]);
        o.z = fmaxf(0.f, b0 * w[i*4+2] + b1 * cc[i*4+2] + b2 * sf[i*4+2]);
        o.w = fmaxf(0.f, b0 * w[i*4+3] + b1 * cc[i*4+3] + b2 * sf[i*4+3]);
        op[i] = o;
    }
}

// ---------------- launch ----------------
extern "C" void kernel_launch(void* const* d_in, const int* in_sizes, int n_in,
                              void* d_out, int out_size)
{
    const float* x_author   = (const float*)d_in[0];
    const float* x_paper    = (const float*)d_in[1];
    const float* W_l_author = (const float*)d_in[2];
    const float* b_l_author = (const float*)d_in[3];
    const float* W_l_paper  = (const float*)d_in[4];
    const float* b_l_paper  = (const float*)d_in[5];
    const float* attn_writes = (const float*)d_in[8];
    const float* attn_cites  = (const float*)d_in[9];
    const float* rel_l = (const float*)d_in[10];
    const float* rel_r = (const float*)d_in[11];
    const int* src_w = (const int*)d_in[12];
    const int* dst_w = (const int*)d_in[13];
    const int* src_c = (const int*)d_in[14];
    const int* dst_c = (const int*)d_in[15];
    const int E = in_sizes[12];
    float* out = (float*)d_out;

    float *l_author, *l_paper, *asw, *asc, *ew, *ec;
    int *cw, *ccnt, *ow, *oc, *curw, *curc, *ssw, *ssc, *bsum, *cbase;
    cudaGetSymbolAddress((void**)&l_author, g_l_author);
    cudaGetSymbolAddress((void**)&l_paper,  g_l_paper);
    cudaGetSymbolAddress((void**)&asw, g_asrc_w);
    cudaGetSymbolAddress((void**)&asc, g_asrc_c);
    cudaGetSymbolAddress((void**)&ew,  g_emb_w);
    cudaGetSymbolAddress((void**)&ec,  g_emb_c);
    cudaGetSymbolAddress((void**)&cw,   g_cnt_w);
    cudaGetSymbolAddress((void**)&ccnt, g_cnt_c);
    cudaGetSymbolAddress((void**)&ow,   g_off_w);
    cudaGetSymbolAddress((void**)&oc,   g_off_c);
    cudaGetSymbolAddress((void**)&curw, g_cur_w);
    cudaGetSymbolAddress((void**)&curc, g_cur_c);
    cudaGetSymbolAddress((void**)&ssw,  g_ssrc_w);
    cudaGetSymbolAddress((void**)&ssc,  g_ssrc_c);
    cudaGetSymbolAddress((void**)&bsum,  g_blocksums);
    cudaGetSymbolAddress((void**)&cbase, g_chunkbase);

    // counting sort of both edge lists by dst
    zero_counts<<<(N_OUT + 255) / 256, 256>>>(cw, ccnt);
    hist_kernel<<<(2 * E + 255) / 256, 256>>>(dst_w, dst_c, cw, ccnt, E);
    {
        dim3 gA(NCHUNKS, 2);
        scanA<<<gA, 256>>>(cw, ccnt, ow, oc, bsum, N_OUT);
        scanB<<<1, 64>>>(bsum, cbase, ow, oc, N_OUT);
        scanC<<<gA, 256>>>(ow, oc, curw, curc, cbase, N_OUT);
    }
    scatter_kernel<<<(2 * E + 255) / 256, 256>>>(src_w, dst_w, src_c, dst_c,
                                                 curw, curc, ssw, ssc, E);

    // projections + per-node source attention logits (alpha_dst cancels -> no r_paper)
    proj_kernel<<<(N_AUTHOR + TMR - 1) / TMR, 256>>>(
        x_author, W_l_author, b_l_author, l_author, N_AUTHOR, attn_writes, C, asw);
    proj_kernel<<<(N_PAPER + TMR - 1) / TMR, 256>>>(
        x_paper, W_l_paper, b_l_paper, l_paper, N_PAPER, attn_cites, C, asc);

    // segmented softmax-weighted aggregation, no atomics
    {
        int blocks = (N_OUT * 32 + 255) / 256;
        gather_kernel<<<blocks, 256>>>(ssw, ow, asw, l_author, ew);
        gather_kernel<<<blocks, 256>>>(ssc, oc, asc, l_paper, ec);
    }

    // semantic attention over {writes, cites, self}
    final_kernel<<<(N_OUT * H + 255) / 256, 256>>>(ew, ec, l_paper, rel_l, rel_r, out);
}

// round 10
// speedup vs baseline: 1.2870x; 1.0465x over previous
#include <cuda_runtime.h>
#include <cstddef>

#define H 4
#define C 16
#define DIN 128
#define DOUT 64
#define N_AUTHOR 150000
#define N_PAPER 200000
#define N_OUT 50000
#define E_MAX 1000000
#define NEG 0.2f

#define CHUNK 2048
#define NCHUNKS ((N_OUT + CHUNK - 1) / CHUNK)   // 25

#define TMR 128
#define KC 16
#define XT_S 136
#define WS_S 72

#define PBA ((N_AUTHOR + TMR - 1) / TMR)        // 1172 proj blocks (author)
#define PBB ((N_PAPER  + TMR - 1) / TMR)        // 1563 proj blocks (paper)
#define SCAT_B 4096                              // scatter grid-stride blocks

// ---------------- scratch (static device arrays; no allocation) ----------------
__device__ float g_l_author[(size_t)N_AUTHOR * DOUT];
__device__ float g_l_paper [(size_t)N_PAPER  * DOUT];
__device__ float g_easrc_w[N_AUTHOR * H];        // exp(alpha_src), writes
__device__ float g_easrc_c[N_PAPER  * H];        // exp(alpha_src), cites
__device__ float g_emb_w [(size_t)N_OUT * DOUT]; // normalized embeddings
__device__ float g_emb_c [(size_t)N_OUT * DOUT];

// counting-sort scratch
__device__ int g_cnt_w[N_OUT];
__device__ int g_cnt_c[N_OUT];
__device__ int g_off_w[N_OUT + 1];
__device__ int g_off_c[N_OUT + 1];
__device__ int g_cur_w[N_OUT];
__device__ int g_cur_c[N_OUT];
__device__ int g_ssrc_w[E_MAX];
__device__ int g_ssrc_c[E_MAX];
__device__ int g_blocksums[2 * 32];
__device__ int g_chunkbase[2 * 32];

__device__ __forceinline__ float lrelu(float x) { return x > 0.f ? x : NEG * x; }

__device__ __forceinline__ unsigned tf32cvt(float f) {
    unsigned u;
    asm("cvt.rna.tf32.f32 %0, %1;" : "=r"(u) : "f"(f));
    return u;
}

__device__ __forceinline__ void mma_tf32(float* c, const unsigned* a, const unsigned* b) {
    asm volatile(
        "mma.sync.aligned.m16n8k8.row.col.f32.tf32.tf32.f32 "
        "{%0,%1,%2,%3}, {%4,%5,%6,%7}, {%8,%9}, {%0,%1,%2,%3};"
        : "+f"(c[0]), "+f"(c[1]), "+f"(c[2]), "+f"(c[3])
        : "r"(a[0]), "r"(a[1]), "r"(a[2]), "r"(a[3]), "r"(b[0]), "r"(b[1]));
}

// ---------------- zero counts ----------------
__global__ void zero_counts(int* cw, int* cc) {
    int i = blockIdx.x * blockDim.x + threadIdx.x;
    if (i < N_OUT) { cw[i] = 0; cc[i] = 0; }
}

// ---------------- counting sort: histogram ----------------
__global__ void hist_kernel(const int* __restrict__ dw, const int* __restrict__ dcst,
                            int* __restrict__ cw, int* __restrict__ cc, int E) {
    int i = blockIdx.x * blockDim.x + threadIdx.x;
    if (i < E)          atomicAdd(&cw[__ldg(&dw[i])], 1);
    else if (i < 2 * E) atomicAdd(&cc[__ldg(&dcst[i - E])], 1);
}

// ---------------- hierarchical exclusive scan ----------------
__global__ void __launch_bounds__(256)
scanA(const int* __restrict__ cw, const int* __restrict__ cc,
      int* __restrict__ ow, int* __restrict__ oc, int* __restrict__ blocksums, int n)
{
    int arr = blockIdx.y;
    const int* counts = arr ? cc : cw;
    int* off = arr ? oc : ow;
    int tid = threadIdx.x, lane = tid & 31, wid = tid >> 5;
    int base = blockIdx.x * CHUNK + tid * 8;

    int v[8], s = 0;
#pragma unroll
    for (int j = 0; j < 8; j++) {
        int i = base + j;
        v[j] = (i < n) ? counts[i] : 0;
        s += v[j];
    }
    int x = s;
#pragma unroll
    for (int o = 1; o < 32; o <<= 1) {
        int t = __shfl_up_sync(0xffffffffu, x, o);
        if (lane >= o) x += t;
    }
    int warp_excl = x - s;

    __shared__ int wsum[8], woff[8];
    if (lane == 31) wsum[wid] = x;
    __syncthreads();
    if (tid < 8) {
        int t = 0;
        for (int k = 0; k < tid; k++) t += wsum[k];
        woff[tid] = t;
    }
    __syncthreads();

    int run = woff[wid] + warp_excl;
#pragma unroll
    for (int j = 0; j < 8; j++) {
        int i = base + j;
        if (i < n) off[i] = run;
        run += v[j];
    }
    if (tid == 255) blocksums[arr * 32 + blockIdx.x] = woff[7] + wsum[7];
}

__global__ void scanB(int* __restrict__ blocksums, int* __restrict__ chunkbase,
                      int* __restrict__ ow, int* __restrict__ oc, int n)
{
    int wid = threadIdx.x >> 5, lane = threadIdx.x & 31;
    if (wid < 2) {
        int v = (lane < NCHUNKS) ? blocksums[wid * 32 + lane] : 0;
        int x = v;
#pragma unroll
        for (int o = 1; o < 32; o <<= 1) {
            int t = __shfl_up_sync(0xffffffffu, x, o);
            if (lane >= o) x += t;
        }
        if (lane < NCHUNKS) chunkbase[wid * 32 + lane] = x - v;
        if (lane == NCHUNKS - 1) {
            if (wid == 0) ow[n] = x; else oc[n] = x;
        }
    }
}

__global__ void __launch_bounds__(256)
scanC(int* __restrict__ ow, int* __restrict__ oc,
      int* __restrict__ curw, int* __restrict__ curc,
      const int* __restrict__ chunkbase, int n)
{
    int arr = blockIdx.y;
    int* off = arr ? oc : ow;
    int* cur = arr ? curc : curw;
    int cb = __ldg(&chunkbase[arr * 32 + blockIdx.x]);
#pragma unroll
    for (int j = 0; j < 8; j++) {
        int i = blockIdx.x * CHUNK + j * 256 + threadIdx.x;
        if (i < n) {
            int t = off[i] + cb;
            off[i] = t;
            cur[i] = t;
        }
    }
}

// ---------------- proj body (device) ----------------
__device__ void proj_body(int pbid,
                          const float* __restrict__ X,
                          const float* __restrict__ Wm,
                          const float* __restrict__ bias,
                          float* __restrict__ Out, int N,
                          const float* __restrict__ attnA, int offA,
                          float* __restrict__ ealphaA)
{
    __shared__ unsigned xsT[2][KC * XT_S];
    __shared__ unsigned wsm[2][KC * WS_S];

    const int tid  = threadIdx.x;
    const int w    = tid >> 5;
    const int lane = tid & 31;
    const int gid  = lane >> 2;
    const int tig  = lane & 3;
    const int row0 = pbid * TMR;

    float4 xr[4];
    float4 wr[2];
    const int wk  = (tid - 128) >> 3;
    const int wn8 = (tid - 128) & 7;

    auto load_regs = [&](int kc) {
        if (tid < TMR) {
            int grow = row0 + tid;
            if (grow < N) {
                const float4* xp = (const float4*)(X + (size_t)grow * DIN + kc * KC);
                xr[0] = xp[0]; xr[1] = xp[1]; xr[2] = xp[2]; xr[3] = xp[3];
            } else {
                xr[0] = xr[1] = xr[2] = xr[3] = make_float4(0.f, 0.f, 0.f, 0.f);
            }
        } else {
            const float4* wp = (const float4*)(Wm + (size_t)(kc * KC + wk) * DOUT + wn8 * 8);
            wr[0] = wp[0]; wr[1] = wp[1];
        }
    };
    auto store_smem = [&](int b) {
        if (tid < TMR) {
            float v[16] = {xr[0].x, xr[0].y, xr[0].z, xr[0].w,
                           xr[1].x, xr[1].y, xr[1].z, xr[1].w,
                           xr[2].x, xr[2].y, xr[2].z, xr[2].w,
                           xr[3].x, xr[3].y, xr[3].z, xr[3].w};
#pragma unroll
            for (int k = 0; k < 16; k++)
                xsT[b][k * XT_S + tid] = tf32cvt(v[k]);
        } else {
            unsigned* wp = &wsm[b][wk * WS_S + wn8 * 8];
            wp[0] = tf32cvt(wr[0].x); wp[1] = tf32cvt(wr[0].y);
            wp[2] = tf32cvt(wr[0].z); wp[3] = tf32cvt(wr[0].w);
            wp[4] = tf32cvt(wr[1].x); wp[5] = tf32cvt(wr[1].y);
            wp[6] = tf32cvt(wr[1].z); wp[7] = tf32cvt(wr[1].w);
        }
    };

    float acc[8][4];
#pragma unroll
    for (int n8 = 0; n8 < 8; n8++)
#pragma unroll
        for (int i = 0; i < 4; i++) acc[n8][i] = 0.f;

    load_regs(0);
    store_smem(0);
    __syncthreads();

    const int r0 = w * 16;
    for (int kc = 0; kc < DIN / KC; kc++) {
        if (kc < 7) load_regs(kc + 1);
        const int b = kc & 1;

#pragma unroll
        for (int ks = 0; ks < KC; ks += 8) {
            unsigned a[4], bb[8][2];
            a[0] = xsT[b][(ks + tig)     * XT_S + r0 + gid];
            a[1] = xsT[b][(ks + tig)     * XT_S + r0 + gid + 8];
            a[2] = xsT[b][(ks + tig + 4) * XT_S + r0 + gid];
            a[3] = xsT[b][(ks + tig + 4) * XT_S + r0 + gid + 8];
#pragma unroll
            for (int n8 = 0; n8 < 8; n8++) {
                bb[n8][0] = wsm[b][(ks + tig)     * WS_S + n8 * 8 + gid];
                bb[n8][1] = wsm[b][(ks + tig + 4) * WS_S + n8 * 8 + gid];
            }
#pragma unroll
            for (int n8 = 0; n8 < 8; n8++) mma_tf32(acc[n8], a, bb[n8]);
        }

        if (kc < 7) {
            __syncthreads();
            store_smem((kc + 1) & 1);
            __syncthreads();
        }
    }

    const int row_lo = row0 + r0 + gid;
    const int row_hi = row_lo + 8;

#pragma unroll
    for (int n8 = 0; n8 < 8; n8++) {
        int col = n8 * 8 + 2 * tig;
        float b0 = __ldg(&bias[col]), b1 = __ldg(&bias[col + 1]);
        acc[n8][0] += b0; acc[n8][1] += b1;
        acc[n8][2] += b0; acc[n8][3] += b1;
        if (row_lo < N)
            *(float2*)(Out + (size_t)row_lo * DOUT + col) = make_float2(acc[n8][0], acc[n8][1]);
        if (row_hi < N)
            *(float2*)(Out + (size_t)row_hi * DOUT + col) = make_float2(acc[n8][2], acc[n8][3]);
    }

#pragma unroll
    for (int h = 0; h < 4; h++) {
        float sAlo = 0.f, sAhi = 0.f;
#pragma unroll
        for (int q = 0; q < 2; q++) {
            int n8 = 2 * h + q;
#pragma unroll
            for (int d = 0; d < 2; d++) {
                int c = q * 8 + 2 * tig + d;
                float av = __ldg(&attnA[h * 2 * C + offA + c]);
                sAlo += lrelu(acc[n8][d])     * av;
                sAhi += lrelu(acc[n8][2 + d]) * av;
            }
        }
        sAlo += __shfl_xor_sync(0xffffffffu, sAlo, 1);
        sAlo += __shfl_xor_sync(0xffffffffu, sAlo, 2);
        sAhi += __shfl_xor_sync(0xffffffffu, sAhi, 1);
        sAhi += __shfl_xor_sync(0xffffffffu, sAhi, 2);
        if (tig == 0) {
            // store exp(alpha): alpha_dst cancels in the segment softmax,
            // and |alpha| is small so exp never overflows.
            if (row_lo < N) ealphaA[row_lo * H + h] = __expf(sAlo);
            if (row_hi < N) ealphaA[row_hi * H + h] = __expf(sAhi);
        }
    }
}

// ---------------- fused mid kernel: proj_author | proj_paper | scatter ----------------
// Independent work co-resident in one launch: tensor-bound proj overlaps
// L2-atomic-bound scatter.
__global__ void __launch_bounds__(256)
mid_kernel(const float* __restrict__ x_author, const float* __restrict__ Wla,
           const float* __restrict__ bla,      float* __restrict__ l_author,
           const float* __restrict__ x_paper,  const float* __restrict__ Wlp,
           const float* __restrict__ blp,      float* __restrict__ l_paper,
           const float* __restrict__ attn_w,   const float* __restrict__ attn_c,
           float* __restrict__ easw,           float* __restrict__ easc,
           const int* __restrict__ sw, const int* __restrict__ dw,
           const int* __restrict__ sc, const int* __restrict__ dcst,
           int* __restrict__ curw, int* __restrict__ curc,
           int* __restrict__ outw, int* __restrict__ outc, int E)
{
    int bid = blockIdx.x;
    if (bid < PBA) {
        proj_body(bid, x_author, Wla, bla, l_author, N_AUTHOR, attn_w, C, easw);
    } else if (bid < PBA + PBB) {
        proj_body(bid - PBA, x_paper, Wlp, blp, l_paper, N_PAPER, attn_c, C, easc);
    } else {
        int sbid = bid - PBA - PBB;
        int tid = threadIdx.x;
        for (int i = sbid * 256 + tid; i < 2 * E; i += SCAT_B * 256) {
            if (i < E) {
                int pos = atomicAdd(&curw[__ldg(&dw[i])], 1);
                outw[pos] = __ldg(&sw[i]);
            } else {
                int j = i - E;
                int pos = atomicAdd(&curc[__ldg(&dcst[j])], 1);
                outc[pos] = __ldg(&sc[j]);
            }
        }
    }
}

// ---------------- fused segmented gather: both metapaths, one warp per dst ----------------
// lane owns cols lane*2, lane*2+1; head h = lane>>3. emb written NORMALIZED.
// easrc already exponentiated.
__global__ void __launch_bounds__(256)
gather_kernel(const int* __restrict__ ssw, const int* __restrict__ ow,
              const float* __restrict__ easw, const float* __restrict__ l_author,
              const int* __restrict__ ssc, const int* __restrict__ oc,
              const float* __restrict__ easc, const float* __restrict__ l_paper,
              float* __restrict__ emb_w, float* __restrict__ emb_c)
{
    int wg = (blockIdx.x * blockDim.x + threadIdx.x) >> 5;
    if (wg >= 2 * N_OUT) return;
    int lane = threadIdx.x & 31;
    int h = lane >> 3;

    const int*   ssrc;
    const int*   offsets;
    const float* easrc;
    const float* lsrc;
    float*       emb;
    int d;
    if (wg < N_OUT) {
        d = wg;          ssrc = ssw; offsets = ow; easrc = easw; lsrc = l_author; emb = emb_w;
    } else {
        d = wg - N_OUT;  ssrc = ssc; offsets = oc; easrc = easc; lsrc = l_paper;  emb = emb_c;
    }

    int beg = __ldg(&offsets[d]);
    int end = __ldg(&offsets[d + 1]);

    float a0 = 0.f, a1 = 0.f, se = 0.f;
    int e = beg;
    for (; e + 4 <= end; e += 4) {
        int s0 = __ldg(&ssrc[e]);
        int s1 = __ldg(&ssrc[e + 1]);
        int s2 = __ldg(&ssrc[e + 2]);
        int s3 = __ldg(&ssrc[e + 3]);
        float ea0 = __ldg(&easrc[s0 * H + h]);
        float ea1 = __ldg(&easrc[s1 * H + h]);
        float ea2 = __ldg(&easrc[s2 * H + h]);
        float ea3 = __ldg(&easrc[s3 * H + h]);
        float2 v0 = *(const float2*)(lsrc + (size_t)s0 * DOUT + lane * 2);
        float2 v1 = *(const float2*)(lsrc + (size_t)s1 * DOUT + lane * 2);
        float2 v2 = *(const float2*)(lsrc + (size_t)s2 * DOUT + lane * 2);
        float2 v3 = *(const float2*)(lsrc + (size_t)s3 * DOUT + lane * 2);
        a0 = fmaf(ea0, v0.x, a0); a1 = fmaf(ea0, v0.y, a1);
        a0 = fmaf(ea1, v1.x, a0); a1 = fmaf(ea1, v1.y, a1);
        a0 = fmaf(ea2, v2.x, a0); a1 = fmaf(ea2, v2.y, a1);
        a0 = fmaf(ea3, v3.x, a0); a1 = fmaf(ea3, v3.y, a1);
        se += ea0 + ea1 + ea2 + ea3;
    }
    for (; e < end; e++) {
        int s0 = __ldg(&ssrc[e]);
        float ea0 = __ldg(&easrc[s0 * H + h]);
        float2 v0 = *(const float2*)(lsrc + (size_t)s0 * DOUT + lane * 2);
        a0 = fmaf(ea0, v0.x, a0); a1 = fmaf(ea0, v0.y, a1);
        se += ea0;
    }
    float inv = 1.f / (se + 1e-16f);
    *(float2*)(emb + (size_t)d * DOUT + lane * 2) = make_float2(a0 * inv, a1 * inv);
}

// ---------------- semantic attention + relu (emb pre-normalized) ----------------
__global__ void final_kernel(const float* __restrict__ emb_w,
                             const float* __restrict__ emb_c,
                             const float* __restrict__ lpap,
                             const float* __restrict__ rel_l, const float* __restrict__ rel_r,
                             float* __restrict__ out)
{
    int idx = blockIdx.x * blockDim.x + threadIdx.x;
    if (idx >= N_OUT * H) return;
    int n = idx >> 2, h = idx & 3;
    size_t base = (size_t)n * DOUT + h * 16;

    float w[16], cc[16], sf[16];
#pragma unroll
    for (int i = 0; i < 4; i++) {
        float4 vw = *(const float4*)(emb_w + base + i * 4);
        float4 vc = *(const float4*)(emb_c + base + i * 4);
        float4 vs = *(const float4*)(lpap  + base + i * 4);
        w[i*4+0] = vw.x; w[i*4+1] = vw.y; w[i*4+2] = vw.z; w[i*4+3] = vw.w;
        cc[i*4+0] = vc.x; cc[i*4+1] = vc.y; cc[i*4+2] = vc.z; cc[i*4+3] = vc.w;
        sf[i*4+0] = vs.x; sf[i*4+1] = vs.y; sf[i*4+2] = vs.z; sf[i*4+3] = vs.w;
    }

    float al = 0.f, a0 = 0.f, a1 = 0.f, a2 = 0.f;
#pragma unroll
    for (int i = 0; i < 16; i++) {
        al += sf[i] * __ldg(&rel_l[h * C + i]);
        a0 += w[i]  * __ldg(&rel_r[0 * H * C + h * C + i]);
        a1 += cc[i] * __ldg(&rel_r[1 * H * C + h * C + i]);
        a2 += sf[i] * __ldg(&rel_r[2 * H * C + h * C + i]);
    }
    float s0 = lrelu(al + a0), s1 = lrelu(al + a1), s2 = lrelu(al + a2);
    float mx = fmaxf(s0, fmaxf(s1, s2));
    float e0 = __expf(s0 - mx), e1 = __expf(s1 - mx), e2 = __expf(s2 - mx);
    float inv = 1.f / (e0 + e1 + e2);
    float b0 = e0 * inv, b1 = e1 * inv, b2 = e2 * inv;

    float4* op = (float4*)(out + base);
#pragma unroll
    for (int i = 0; i < 4; i++) {
        float4 o;
        o.x = fmaxf(0.f, b0 * w[i*4+0] + b1 * cc[i*4+0] + b2 * sf[i*4+0]);
        o.y = fmaxf(0.f, b0 * w[i*4+1] + b1 * cc[i*4+1] + b2 * sf[i*4+1]);
        o.z = fmaxf(0.f, b0 * w[i*4+2] + b1 * cc[i*4+2] + b2 * sf[i*4+2]);
        o.w = fmaxf(0.f, b0 * w[i*4+3] + b1 * cc[i*4+3] + b2 * sf[i*4+3]);
        op[i] = o;
    }
}

// ---------------- launch ----------------
extern "C" void kernel_launch(void* const* d_in, const int* in_sizes, int n_in,
                              void* d_out, int out_size)
{
    const float* x_author   = (const float*)d_in[0];
    const float* x_paper    = (const float*)d_in[1];
    const float* W_l_author = (const float*)d_in[2];
    const float* b_l_author = (const float*)d_in[3];
    const float* W_l_paper  = (const float*)d_in[4];
    const float* b_l_paper  = (const float*)d_in[5];
    const float* attn_writes = (const float*)d_in[8];
    const float* attn_cites  = (const float*)d_in[9];
    const float* rel_l = (const float*)d_in[10];
    const float* rel_r = (const float*)d_in[11];
    const int* src_w = (const int*)d_in[12];
    const int* dst_w = (const int*)d_in[13];
    const int* src_c = (const int*)d_in[14];
    const int* dst_c = (const int*)d_in[15];
    const int E = in_sizes[12];
    float* out = (float*)d_out;

    float *l_author, *l_paper, *easw, *easc, *ew, *ec;
    int *cw, *ccnt, *ow, *oc, *curw, *curc, *ssw, *ssc, *bsum, *cbase;
    cudaGetSymbolAddress((void**)&l_author, g_l_author);
    cudaGetSymbolAddress((void**)&l_paper,  g_l_paper);
    cudaGetSymbolAddress((void**)&easw, g_easrc_w);
    cudaGetSymbolAddress((void**)&easc, g_easrc_c);
    cudaGetSymbolAddress((void**)&ew,  g_emb_w);
    cudaGetSymbolAddress((void**)&ec,  g_emb_c);
    cudaGetSymbolAddress((void**)&cw,   g_cnt_w);
    cudaGetSymbolAddress((void**)&ccnt, g_cnt_c);
    cudaGetSymbolAddress((void**)&ow,   g_off_w);
    cudaGetSymbolAddress((void**)&oc,   g_off_c);
    cudaGetSymbolAddress((void**)&curw, g_cur_w);
    cudaGetSymbolAddress((void**)&curc, g_cur_c);
    cudaGetSymbolAddress((void**)&ssw,  g_ssrc_w);
    cudaGetSymbolAddress((void**)&ssc,  g_ssrc_c);
    cudaGetSymbolAddress((void**)&bsum,  g_blocksums);
    cudaGetSymbolAddress((void**)&cbase, g_chunkbase);

    // counting-sort prefix: counts + offsets + cursors
    zero_counts<<<(N_OUT + 255) / 256, 256>>>(cw, ccnt);
    hist_kernel<<<(2 * E + 255) / 256, 256>>>(dst_w, dst_c, cw, ccnt, E);
    {
        dim3 gA(NCHUNKS, 2);
        scanA<<<gA, 256>>>(cw, ccnt, ow, oc, bsum, N_OUT);
        scanB<<<1, 64>>>(bsum, cbase, ow, oc, N_OUT);
        scanC<<<gA, 256>>>(ow, oc, curw, curc, cbase, N_OUT);
    }

    // fused: both projections (tensor-bound) + edge scatter (L2-atomic-bound)
    mid_kernel<<<PBA + PBB + SCAT_B, 256>>>(
        x_author, W_l_author, b_l_author, l_author,
        x_paper,  W_l_paper,  b_l_paper,  l_paper,
        attn_writes, attn_cites, easw, easc,
        src_w, dst_w, src_c, dst_c, curw, curc, ssw, ssc, E);

    // fused segmented softmax-weighted aggregation, both metapaths, no atomics
    gather_kernel<<<(2 * N_OUT * 32 + 255) / 256, 256>>>(
        ssw, ow, easw, l_author, ssc, oc, easc, l_paper, ew, ec);

    // semantic attention over {writes, cites, self}
    final_kernel<<<(N_OUT * H + 255) / 256, 256>>>(ew, ec, l_paper, rel_l, rel_r, out);
}